// round 10
// baseline (speedup 1.0000x reference)
#include <cuda_runtime.h>
#include <cuda_fp16.h>

#define NN 100000
#define EMAX 800000
#define NBLK ((NN + 255) / 256)  // 391

// ---------------- device scratch (no allocations allowed) ----------------
__device__ __align__(16) __half2 g_hs16[NN * 32];   // h1*dinv fp16 [N,64] (128B/row)
__device__ __align__(16) float4 g_agg[NN * 16];     // layer1 aggregate fp32
__device__ __align__(16) __half2 g_h2s16[NN * 8];   // h2*dinv fp16 [N,16] (32B/row)
__device__ unsigned g_deg[NN];       // zero at call start (agg2 resets)
__device__ unsigned g_rowstart[NN];
__device__ unsigned g_cursor[NN];
__device__ unsigned g_total;         // zero at call start (agg2 resets)
__device__ int g_csr[EMAX];          // source ids grouped by target
__device__ float g_dinv[NN];

// ---------------- packed fp32x2 FMA (Blackwell; PTX-only) -----------------
union F2 { unsigned long long u; float2 f; };
__device__ __forceinline__ void fma2(F2& d, F2 a, F2 b) {
    asm("fma.rn.f32x2 %0, %1, %2, %0;" : "+l"(d.u) : "l"(a.u), "l"(b.u));
}
__device__ __forceinline__ F2 pack2(float lo, float hi) {
    F2 r; r.f = make_float2(lo, hi); return r;
}

// int64-vs-int32 detection (full-warp). Little-endian int64 with ids<100000
// => every odd int32 slot is 0; for int32 those slots are random ids.
__device__ __forceinline__ bool detect64(const int* __restrict__ e32) {
    int v = __ldg(&e32[2 * (threadIdx.x & 31) + 1]);
    return __ballot_sync(0xffffffffu, v != 0) == 0u;
}
__device__ __forceinline__ int load_idx(const int* __restrict__ e32, int i, bool is64) {
    return __ldg(&e32[is64 ? 2 * (long long)i : (long long)i]);
}
__device__ __forceinline__ int load_idx2(const int* __restrict__ e32, int E, int i,
                                         bool is64) {
    return __ldg(&e32[is64 ? 2 * ((long long)E + i) : (long long)(E + i)]);
}

// ---------------- degree histogram ----------------
__global__ void deg_count_kernel(const int* __restrict__ e32, int E) {
    bool is64 = detect64(e32);
    int t = blockIdx.x * blockDim.x + threadIdx.x;
    if (t >= E) return;
    atomicAdd(&g_deg[load_idx2(e32, E, t, is64)], 1u);
}

// ---------------- fused scan + dinv ----------------
// Block-local exclusive scan; block offset via atomicAdd completion order
// (disjoint ranges; only CSR segment placement varies -> fp32 order noise).
__global__ void scan_fused_kernel() {
    int tid = threadIdx.x, lane = tid & 31, wid = tid >> 5;
    int i = blockIdx.x * 256 + tid;
    unsigned v = (i < NN) ? g_deg[i] : 0u;
    unsigned s = v;
#pragma unroll
    for (int d = 1; d < 32; d <<= 1) {
        unsigned n = __shfl_up_sync(0xffffffffu, s, d);
        if (lane >= d) s += n;
    }
    __shared__ unsigned wt[8];
    __shared__ unsigned s_off;
    if (lane == 31) wt[wid] = s;
    __syncthreads();
    if (tid < 8) {
        unsigned w = wt[tid], ws = w;
#pragma unroll
        for (int d = 1; d < 8; d <<= 1) {
            unsigned n = __shfl_up_sync(0xffu, ws, d);
            if (tid >= d) ws += n;
        }
        wt[tid] = ws - w;  // exclusive
        if (tid == 7) s_off = atomicAdd(&g_total, ws);  // block total
    }
    __syncthreads();
    if (i < NN) {
        unsigned rs = s - v + wt[wid] + s_off;
        g_rowstart[i] = rs;
        g_cursor[i] = rs;
        g_dinv[i] = rsqrtf((float)(v + 1u));
    }
}

// ---------------- CSR fill ----------------
__global__ void csr_fill_kernel(const int* __restrict__ e32, int E) {
    bool is64 = detect64(e32);
    int t = blockIdx.x * blockDim.x + threadIdx.x;
    if (t >= E) return;
    int r = load_idx(e32, t, is64);
    int c = load_idx2(e32, E, t, is64);
    unsigned pos = atomicAdd(&g_cursor[c], 1u);
    g_csr[pos] = r;
}

// mm1: 4 threads/row, each computes 16 output cols with packed f32x2 FMA.
// hs16 = (x@W1)*dinv stored fp16.
__global__ void __launch_bounds__(256) mm1_kernel(const float4* __restrict__ X4,
                                                  const float* __restrict__ W) {
    __shared__ float4 sW[64 * 16];  // W1 64x64: sW[k*16+c4] = cols 4c4..4c4+3 of k
    for (int i = threadIdx.x; i < 64 * 16; i += 256) sW[i] = ((const float4*)W)[i];
    __syncthreads();
    int t = blockIdx.x * 256 + threadIdx.x;
    int row = t >> 2, qtr = t & 3;
    if (row >= NN) return;
    float dv = __ldg(&g_dinv[row]);

    F2 acc[8];  // col pairs (qtr*16+2j, qtr*16+2j+1)
#pragma unroll
    for (int j = 0; j < 8; j++) acc[j].f = make_float2(0.f, 0.f);
    const float4* wbase = &sW[qtr * 4];
#pragma unroll 4
    for (int k4 = 0; k4 < 16; k4++) {
        float4 xv = __ldg(&X4[(long long)row * 16 + k4]);
        float xs4[4] = {xv.x, xv.y, xv.z, xv.w};
#pragma unroll
        for (int c = 0; c < 4; c++) {
            F2 xx = pack2(xs4[c], xs4[c]);
            const float4* wr = wbase + (k4 * 4 + c) * 16;
#pragma unroll
            for (int j2 = 0; j2 < 4; j2++) {
                float4 w = wr[j2];
                fma2(acc[2 * j2 + 0], xx, pack2(w.x, w.y));
                fma2(acc[2 * j2 + 1], xx, pack2(w.z, w.w));
            }
        }
    }
    // 8 packed pairs -> 8 half2 = 2 uint4 stores; slot j = col pair directly.
    union { __half2 h[8]; uint4 u[2]; } pk;
#pragma unroll
    for (int j = 0; j < 8; j++)
        pk.h[j] = __floats2half2_rn(acc[j].f.x * dv, acc[j].f.y * dv);
    *(uint4*)&g_hs16[row * 32 + qtr * 8 + 0] = pk.u[0];
    *(uint4*)&g_hs16[row * 32 + qtr * 8 + 4] = pk.u[1];
}

// ---------------- layer1 aggregate: warp/node, preloaded ids, unrolled ----
__global__ void __launch_bounds__(256) agg1_kernel() {
    int node = blockIdx.x * 8 + (threadIdx.x >> 5);
    if (node >= NN) return;
    int lane = threadIdx.x & 31;
    int q = lane & 15, sub = lane >> 4;
    unsigned start = g_rowstart[node];
    unsigned cnt = g_deg[node];
    float4 acc = make_float4(0.f, 0.f, 0.f, 0.f);
    for (unsigned base = 0; base < cnt; base += 32) {
        unsigned n = cnt - base;
        if (n > 32u) n = 32u;
        int id = __ldg(&g_csr[start + base + (lane < n ? lane : n - 1)]);
#pragma unroll 4
        for (unsigned j = 0; j < n; j += 2) {  // n warp-uniform
            unsigned jj = j + sub;
            int rr = __shfl_sync(0xffffffffu, id, jj < n ? jj : n - 1);
            if (jj < n) {
                uint2 u = __ldg((const uint2*)&g_hs16[rr * 32 + 2 * q]);
                float2 f0 = __half22float2(*(__half2*)&u.x);
                float2 f1 = __half22float2(*(__half2*)&u.y);
                acc.x += f0.x; acc.y += f0.y; acc.z += f1.x; acc.w += f1.y;
            }
        }
    }
    acc.x += __shfl_xor_sync(0xffffffffu, acc.x, 16);
    acc.y += __shfl_xor_sync(0xffffffffu, acc.y, 16);
    acc.z += __shfl_xor_sync(0xffffffffu, acc.z, 16);
    acc.w += __shfl_xor_sync(0xffffffffu, acc.w, 16);
    if (sub == 0) {  // add self-loop message, single coalesced write
        uint2 u = __ldg((const uint2*)&g_hs16[node * 32 + 2 * q]);
        float2 f0 = __half22float2(*(__half2*)&u.x);
        float2 f1 = __half22float2(*(__half2*)&u.y);
        g_agg[node * 16 + q] =
            make_float4(acc.x + f0.x, acc.y + f0.y, acc.z + f1.x, acc.w + f1.y);
    }
}

// mm2: 2 threads/row, 8 cols each via f32x2; a = relu(agg*dinv+b1);
// h2s16 = (a@W2)*dinv.
__global__ void __launch_bounds__(256) mm2_kernel(const float* __restrict__ W2,
                                                  const float* __restrict__ b1) {
    __shared__ float4 sW[64 * 4];  // W2 64x16
    __shared__ float4 sB1[16];
    for (int i = threadIdx.x; i < 64 * 4; i += 256) sW[i] = ((const float4*)W2)[i];
    if (threadIdx.x < 16) sB1[threadIdx.x] = ((const float4*)b1)[threadIdx.x];
    __syncthreads();
    int t = blockIdx.x * 256 + threadIdx.x;
    int row = t >> 1, half = t & 1;
    if (row >= NN) return;
    float dv = g_dinv[row];
    F2 acc[4];
#pragma unroll
    for (int j = 0; j < 4; j++) acc[j].f = make_float2(0.f, 0.f);
    const float4* wbase = &sW[half * 2];
#pragma unroll 4
    for (int k4 = 0; k4 < 16; k4++) {
        float4 a = g_agg[row * 16 + k4];
        float4 bb = sB1[k4];
        float as4[4];
        as4[0] = fmaxf(fmaf(a.x, dv, bb.x), 0.f);
        as4[1] = fmaxf(fmaf(a.y, dv, bb.y), 0.f);
        as4[2] = fmaxf(fmaf(a.z, dv, bb.z), 0.f);
        as4[3] = fmaxf(fmaf(a.w, dv, bb.w), 0.f);
#pragma unroll
        for (int c = 0; c < 4; c++) {
            F2 xx = pack2(as4[c], as4[c]);
            const float4* wr = wbase + (k4 * 4 + c) * 4;
            float4 w0 = wr[0], w1 = wr[1];
            fma2(acc[0], xx, pack2(w0.x, w0.y));
            fma2(acc[1], xx, pack2(w0.z, w0.w));
            fma2(acc[2], xx, pack2(w1.x, w1.y));
            fma2(acc[3], xx, pack2(w1.z, w1.w));
        }
    }
    union { __half2 h[4]; uint4 u; } pk;
#pragma unroll
    for (int j = 0; j < 4; j++)
        pk.h[j] = __floats2half2_rn(acc[j].f.x * dv, acc[j].f.y * dv);
    *(uint4*)&g_h2s16[row * 8 + half * 4] = pk.u;
}

// ---------------- layer2 aggregate + finalize: warp/node, 8 nbrs/iter -----
__global__ void __launch_bounds__(256) agg2_kernel(const float4* __restrict__ b2,
                                                   float4* __restrict__ out4) {
    int node = blockIdx.x * 8 + (threadIdx.x >> 5);
    if (node >= NN) return;
    int lane = threadIdx.x & 31;
    int q = lane & 3, sub = lane >> 2;
    unsigned start = g_rowstart[node];
    unsigned cnt = g_deg[node];
    float4 acc = make_float4(0.f, 0.f, 0.f, 0.f);
    for (unsigned base = 0; base < cnt; base += 32) {
        unsigned n = cnt - base;
        if (n > 32u) n = 32u;
        int id = __ldg(&g_csr[start + base + (lane < n ? lane : n - 1)]);
#pragma unroll 2
        for (unsigned j = 0; j < n; j += 8) {
            unsigned jj = j + sub;
            int rr = __shfl_sync(0xffffffffu, id, jj < n ? jj : n - 1);
            if (jj < n) {
                uint2 u = __ldg((const uint2*)&g_h2s16[rr * 8 + 2 * q]);
                float2 f0 = __half22float2(*(__half2*)&u.x);
                float2 f1 = __half22float2(*(__half2*)&u.y);
                acc.x += f0.x; acc.y += f0.y; acc.z += f1.x; acc.w += f1.y;
            }
        }
    }
#pragma unroll
    for (int d = 4; d < 32; d <<= 1) {
        acc.x += __shfl_xor_sync(0xffffffffu, acc.x, d);
        acc.y += __shfl_xor_sync(0xffffffffu, acc.y, d);
        acc.z += __shfl_xor_sync(0xffffffffu, acc.z, d);
        acc.w += __shfl_xor_sync(0xffffffffu, acc.w, d);
    }
    if (lane == 0) g_deg[node] = 0u;             // reset for next replay
    if (node == 0 && lane == 1) g_total = 0u;    // reset scan base
    if (sub == 0) {
        uint2 u = __ldg((const uint2*)&g_h2s16[node * 8 + 2 * q]);
        float2 f0 = __half22float2(*(__half2*)&u.x);
        float2 f1 = __half22float2(*(__half2*)&u.y);
        float dv = __ldg(&g_dinv[node]);
        float4 bv = __ldg(&b2[q]);
        out4[node * 4 + q] =
            make_float4(fmaf(acc.x + f0.x, dv, bv.x), fmaf(acc.y + f0.y, dv, bv.y),
                        fmaf(acc.z + f1.x, dv, bv.z), fmaf(acc.w + f1.y, dv, bv.w));
    }
}

// ---------------- launch ----------------
extern "C" void kernel_launch(void* const* d_in, const int* in_sizes, int n_in,
                              void* d_out, int out_size) {
    const float* x = (const float*)d_in[0];
    const int* e32 = (const int*)d_in[1];
    const float* W1 = (const float*)d_in[2];
    const float* b1 = (const float*)d_in[3];
    const float* W2 = (const float*)d_in[4];
    const float* b2 = (const float*)d_in[5];
    int E = in_sizes[1] / 2;
    if (E > EMAX) E = EMAX;

    deg_count_kernel<<<(E + 255) / 256, 256>>>(e32, E);
    scan_fused_kernel<<<NBLK, 256>>>();
    csr_fill_kernel<<<(E + 255) / 256, 256>>>(e32, E);
    mm1_kernel<<<(NN * 4 + 255) / 256, 256>>>((const float4*)x, W1);
    agg1_kernel<<<(NN + 7) / 8, 256>>>();
    mm2_kernel<<<(NN * 2 + 255) / 256, 256>>>(W2, b1);
    agg2_kernel<<<(NN + 7) / 8, 256>>>((const float4*)b2, (float4*)d_out);
}

// round 11
// speedup vs baseline: 1.4574x; 1.4574x over previous
#include <cuda_runtime.h>
#include <cuda_fp16.h>

#define NN 100000
#define EMAX 800000
#define NBLK ((NN + 255) / 256)  // 391

// ---------------- device scratch (no allocations allowed) ----------------
__device__ __align__(16) __half2 g_hs16[NN * 32];   // h1*dinv fp16 [N,64] (128B/row)
__device__ __align__(16) float4 g_agg[NN * 16];     // layer1 aggregate fp32
__device__ __align__(16) __half2 g_h2s16[NN * 8];   // h2*dinv fp16 [N,16] (32B/row)
__device__ unsigned g_deg[NN];       // zero at call start (agg2 resets)
__device__ unsigned g_rowstart[NN];
__device__ unsigned g_cursor[NN];
__device__ unsigned g_total;         // zero at call start (agg2 resets)
__device__ int g_csr[EMAX];          // source ids grouped by target
__device__ float g_dinv[NN];

// ---------------- packed fp32x2 FMA (Blackwell; PTX-only) -----------------
union F2 { unsigned long long u; float2 f; };
__device__ __forceinline__ void fma2(F2& d, F2 a, F2 b) {
    asm("fma.rn.f32x2 %0, %1, %2, %0;" : "+l"(d.u) : "l"(a.u), "l"(b.u));
}
__device__ __forceinline__ F2 pack2(float lo, float hi) {
    F2 r; r.f = make_float2(lo, hi); return r;
}

// int64-vs-int32 detection (full-warp). Little-endian int64 with ids<100000
// => every odd int32 slot is 0; for int32 those slots are random ids.
__device__ __forceinline__ bool detect64(const int* __restrict__ e32) {
    int v = __ldg(&e32[2 * (threadIdx.x & 31) + 1]);
    return __ballot_sync(0xffffffffu, v != 0) == 0u;
}
__device__ __forceinline__ int load_idx(const int* __restrict__ e32, int i, bool is64) {
    return __ldg(&e32[is64 ? 2 * (long long)i : (long long)i]);
}
__device__ __forceinline__ int load_idx2(const int* __restrict__ e32, int E, int i,
                                         bool is64) {
    return __ldg(&e32[is64 ? 2 * ((long long)E + i) : (long long)(E + i)]);
}

// ---------------- degree histogram ----------------
__global__ void deg_count_kernel(const int* __restrict__ e32, int E) {
    bool is64 = detect64(e32);
    int t = blockIdx.x * blockDim.x + threadIdx.x;
    if (t >= E) return;
    atomicAdd(&g_deg[load_idx2(e32, E, t, is64)], 1u);
}

// ---------------- fused scan + dinv ----------------
// Block-local exclusive scan; block offset via atomicAdd completion order
// (disjoint ranges; only CSR segment placement varies -> fp32 order noise).
__global__ void scan_fused_kernel() {
    int tid = threadIdx.x, lane = tid & 31, wid = tid >> 5;
    int i = blockIdx.x * 256 + tid;
    unsigned v = (i < NN) ? g_deg[i] : 0u;
    unsigned s = v;
#pragma unroll
    for (int d = 1; d < 32; d <<= 1) {
        unsigned n = __shfl_up_sync(0xffffffffu, s, d);
        if (lane >= d) s += n;
    }
    __shared__ unsigned wt[8];
    __shared__ unsigned s_off;
    if (lane == 31) wt[wid] = s;
    __syncthreads();
    if (tid < 8) {
        unsigned w = wt[tid], ws = w;
#pragma unroll
        for (int d = 1; d < 8; d <<= 1) {
            unsigned n = __shfl_up_sync(0xffu, ws, d);
            if (tid >= d) ws += n;
        }
        wt[tid] = ws - w;  // exclusive
        if (tid == 7) s_off = atomicAdd(&g_total, ws);  // block total
    }
    __syncthreads();
    if (i < NN) {
        unsigned rs = s - v + wt[wid] + s_off;
        g_rowstart[i] = rs;
        g_cursor[i] = rs;
        g_dinv[i] = rsqrtf((float)(v + 1u));
    }
}

// ---------------- CSR fill ----------------
__global__ void csr_fill_kernel(const int* __restrict__ e32, int E) {
    bool is64 = detect64(e32);
    int t = blockIdx.x * blockDim.x + threadIdx.x;
    if (t >= E) return;
    int r = load_idx(e32, t, is64);
    int c = load_idx2(e32, E, t, is64);
    unsigned pos = atomicAdd(&g_cursor[c], 1u);
    g_csr[pos] = r;
}

// mm1: ONE thread per row, all 64 output cols as 32 packed f32x2 accums.
// All lanes read the SAME sW address each step -> smem broadcast (1 phase).
// hs16 = (x@W1)*dinv stored fp16.
__global__ void __launch_bounds__(256) mm1_kernel(const float4* __restrict__ X4,
                                                  const float* __restrict__ W) {
    __shared__ float4 sW[64 * 16];  // sW[k*16 + c4] = W[k][4c4..4c4+3]
    for (int i = threadIdx.x; i < 64 * 16; i += 256) sW[i] = ((const float4*)W)[i];
    __syncthreads();
    int row = blockIdx.x * 256 + threadIdx.x;
    if (row >= NN) return;
    float dv = __ldg(&g_dinv[row]);

    F2 acc[32];  // col pair j = cols (2j, 2j+1)
#pragma unroll
    for (int j = 0; j < 32; j++) acc[j].f = make_float2(0.f, 0.f);
#pragma unroll 2
    for (int k4 = 0; k4 < 16; k4++) {
        float4 xv = __ldg(&X4[(long long)row * 16 + k4]);
        float xs4[4] = {xv.x, xv.y, xv.z, xv.w};
#pragma unroll
        for (int c = 0; c < 4; c++) {
            F2 xx = pack2(xs4[c], xs4[c]);
            const float4* wr = &sW[(k4 * 4 + c) * 16];  // warp-uniform address
#pragma unroll
            for (int j2 = 0; j2 < 16; j2++) {
                float4 w = wr[j2];
                fma2(acc[2 * j2 + 0], xx, pack2(w.x, w.y));
                fma2(acc[2 * j2 + 1], xx, pack2(w.z, w.w));
            }
        }
    }
    // 32 packed pairs -> 32 half2 = 4x uint4 stores; slot j = col pair j.
#pragma unroll
    for (int g = 0; g < 4; g++) {
        union { __half2 h[8]; uint4 u[2]; } pk;
#pragma unroll
        for (int j = 0; j < 8; j++)
            pk.h[j] = __floats2half2_rn(acc[g * 8 + j].f.x * dv,
                                        acc[g * 8 + j].f.y * dv);
        *(uint4*)&g_hs16[row * 32 + g * 8 + 0] = pk.u[0];
        *(uint4*)&g_hs16[row * 32 + g * 8 + 4] = pk.u[1];
    }
}

// ---------------- layer1 aggregate: warp/node, preloaded ids, unrolled ----
__global__ void __launch_bounds__(256) agg1_kernel() {
    int node = blockIdx.x * 8 + (threadIdx.x >> 5);
    if (node >= NN) return;
    int lane = threadIdx.x & 31;
    int q = lane & 15, sub = lane >> 4;
    unsigned start = g_rowstart[node];
    unsigned cnt = g_deg[node];
    float4 acc = make_float4(0.f, 0.f, 0.f, 0.f);
    for (unsigned base = 0; base < cnt; base += 32) {
        unsigned n = cnt - base;
        if (n > 32u) n = 32u;
        int id = __ldg(&g_csr[start + base + (lane < n ? lane : n - 1)]);
#pragma unroll 4
        for (unsigned j = 0; j < n; j += 2) {  // n warp-uniform
            unsigned jj = j + sub;
            int rr = __shfl_sync(0xffffffffu, id, jj < n ? jj : n - 1);
            if (jj < n) {
                uint2 u = __ldg((const uint2*)&g_hs16[rr * 32 + 2 * q]);
                float2 f0 = __half22float2(*(__half2*)&u.x);
                float2 f1 = __half22float2(*(__half2*)&u.y);
                acc.x += f0.x; acc.y += f0.y; acc.z += f1.x; acc.w += f1.y;
            }
        }
    }
    acc.x += __shfl_xor_sync(0xffffffffu, acc.x, 16);
    acc.y += __shfl_xor_sync(0xffffffffu, acc.y, 16);
    acc.z += __shfl_xor_sync(0xffffffffu, acc.z, 16);
    acc.w += __shfl_xor_sync(0xffffffffu, acc.w, 16);
    if (sub == 0) {  // add self-loop message, single coalesced write
        uint2 u = __ldg((const uint2*)&g_hs16[node * 32 + 2 * q]);
        float2 f0 = __half22float2(*(__half2*)&u.x);
        float2 f1 = __half22float2(*(__half2*)&u.y);
        g_agg[node * 16 + q] =
            make_float4(acc.x + f0.x, acc.y + f0.y, acc.z + f1.x, acc.w + f1.y);
    }
}

// mm2: 2 threads/row, 8 cols each via f32x2; a = relu(agg*dinv+b1);
// h2s16 = (a@W2)*dinv.
__global__ void __launch_bounds__(256) mm2_kernel(const float* __restrict__ W2,
                                                  const float* __restrict__ b1) {
    __shared__ float4 sW[64 * 4];  // W2 64x16
    __shared__ float4 sB1[16];
    for (int i = threadIdx.x; i < 64 * 4; i += 256) sW[i] = ((const float4*)W2)[i];
    if (threadIdx.x < 16) sB1[threadIdx.x] = ((const float4*)b1)[threadIdx.x];
    __syncthreads();
    int t = blockIdx.x * 256 + threadIdx.x;
    int row = t >> 1, half = t & 1;
    if (row >= NN) return;
    float dv = g_dinv[row];
    F2 acc[4];
#pragma unroll
    for (int j = 0; j < 4; j++) acc[j].f = make_float2(0.f, 0.f);
    const float4* wbase = &sW[half * 2];
#pragma unroll 4
    for (int k4 = 0; k4 < 16; k4++) {
        float4 a = g_agg[row * 16 + k4];
        float4 bb = sB1[k4];
        float as4[4];
        as4[0] = fmaxf(fmaf(a.x, dv, bb.x), 0.f);
        as4[1] = fmaxf(fmaf(a.y, dv, bb.y), 0.f);
        as4[2] = fmaxf(fmaf(a.z, dv, bb.z), 0.f);
        as4[3] = fmaxf(fmaf(a.w, dv, bb.w), 0.f);
#pragma unroll
        for (int c = 0; c < 4; c++) {
            F2 xx = pack2(as4[c], as4[c]);
            const float4* wr = wbase + (k4 * 4 + c) * 4;
            float4 w0 = wr[0], w1 = wr[1];
            fma2(acc[0], xx, pack2(w0.x, w0.y));
            fma2(acc[1], xx, pack2(w0.z, w0.w));
            fma2(acc[2], xx, pack2(w1.x, w1.y));
            fma2(acc[3], xx, pack2(w1.z, w1.w));
        }
    }
    union { __half2 h[4]; uint4 u; } pk;
#pragma unroll
    for (int j = 0; j < 4; j++)
        pk.h[j] = __floats2half2_rn(acc[j].f.x * dv, acc[j].f.y * dv);
    *(uint4*)&g_h2s16[row * 8 + half * 4] = pk.u;
}

// ---------------- layer2 aggregate + finalize: warp/node, 8 nbrs/iter -----
__global__ void __launch_bounds__(256) agg2_kernel(const float4* __restrict__ b2,
                                                   float4* __restrict__ out4) {
    int node = blockIdx.x * 8 + (threadIdx.x >> 5);
    if (node >= NN) return;
    int lane = threadIdx.x & 31;
    int q = lane & 3, sub = lane >> 2;
    unsigned start = g_rowstart[node];
    unsigned cnt = g_deg[node];
    float4 acc = make_float4(0.f, 0.f, 0.f, 0.f);
    for (unsigned base = 0; base < cnt; base += 32) {
        unsigned n = cnt - base;
        if (n > 32u) n = 32u;
        int id = __ldg(&g_csr[start + base + (lane < n ? lane : n - 1)]);
#pragma unroll 2
        for (unsigned j = 0; j < n; j += 8) {
            unsigned jj = j + sub;
            int rr = __shfl_sync(0xffffffffu, id, jj < n ? jj : n - 1);
            if (jj < n) {
                uint2 u = __ldg((const uint2*)&g_h2s16[rr * 8 + 2 * q]);
                float2 f0 = __half22float2(*(__half2*)&u.x);
                float2 f1 = __half22float2(*(__half2*)&u.y);
                acc.x += f0.x; acc.y += f0.y; acc.z += f1.x; acc.w += f1.y;
            }
        }
    }
#pragma unroll
    for (int d = 4; d < 32; d <<= 1) {
        acc.x += __shfl_xor_sync(0xffffffffu, acc.x, d);
        acc.y += __shfl_xor_sync(0xffffffffu, acc.y, d);
        acc.z += __shfl_xor_sync(0xffffffffu, acc.z, d);
        acc.w += __shfl_xor_sync(0xffffffffu, acc.w, d);
    }
    if (lane == 0) g_deg[node] = 0u;             // reset for next replay
    if (node == 0 && lane == 1) g_total = 0u;    // reset scan base
    if (sub == 0) {
        uint2 u = __ldg((const uint2*)&g_h2s16[node * 8 + 2 * q]);
        float2 f0 = __half22float2(*(__half2*)&u.x);
        float2 f1 = __half22float2(*(__half2*)&u.y);
        float dv = __ldg(&g_dinv[node]);
        float4 bv = __ldg(&b2[q]);
        out4[node * 4 + q] =
            make_float4(fmaf(acc.x + f0.x, dv, bv.x), fmaf(acc.y + f0.y, dv, bv.y),
                        fmaf(acc.z + f1.x, dv, bv.z), fmaf(acc.w + f1.y, dv, bv.w));
    }
}

// ---------------- launch ----------------
extern "C" void kernel_launch(void* const* d_in, const int* in_sizes, int n_in,
                              void* d_out, int out_size) {
    const float* x = (const float*)d_in[0];
    const int* e32 = (const int*)d_in[1];
    const float* W1 = (const float*)d_in[2];
    const float* b1 = (const float*)d_in[3];
    const float* W2 = (const float*)d_in[4];
    const float* b2 = (const float*)d_in[5];
    int E = in_sizes[1] / 2;
    if (E > EMAX) E = EMAX;

    deg_count_kernel<<<(E + 255) / 256, 256>>>(e32, E);
    scan_fused_kernel<<<NBLK, 256>>>();
    csr_fill_kernel<<<(E + 255) / 256, 256>>>(e32, E);
    mm1_kernel<<<(NN + 255) / 256, 256>>>((const float4*)x, W1);
    agg1_kernel<<<(NN + 7) / 8, 256>>>();
    mm2_kernel<<<(NN * 2 + 255) / 256, 256>>>(W2, b1);
    agg2_kernel<<<(NN + 7) / 8, 256>>>((const float4*)b2, (float4*)d_out);
}